// round 1
// baseline (speedup 1.0000x reference)
#include <cuda_runtime.h>
#include <cuda_bf16.h>
#include <math.h>

// Problem constants
#define BB 8
#define TT 16
#define HH 64
#define WW 64
#define CIN 32
#define FF 64
#define G4 256           // 4*F gate channels
#define CK 96            // CIN + FF fused input channels
#define HW 4096          // H*W
#define STATE_N (BB*HW*FF)        // 2,097,152 floats per state tensor
#define Z_N (BB*HW*G4)            // 8,388,608 floats per z scratch
#define WF_N (3*3*CK*G4)          // 221,184 floats fused weights

// ---------------- static device scratch (no allocations allowed) -------------
__device__ float g_Wf[2][WF_N];
__device__ float g_h[2][STATE_N];
__device__ float g_c[2][STATE_N];
__device__ float g_z[2][Z_N];

// ---------------- weight fusion: [3,3,96,256] from Wx[3,3,32,256]+Wh[3,3,64,256]
__global__ void fuse_weights_kernel(const float* __restrict__ Wx,
                                    const float* __restrict__ Wh,
                                    float* __restrict__ Wf) {
    int i = blockIdx.x * blockDim.x + threadIdx.x;
    if (i >= WF_N) return;
    int cout = i & 255;
    int cin  = (i >> 8) % CK;
    int kk   = i / (256 * CK);  // ky*3+kx, 0..8
    float v;
    if (cin < CIN) v = Wx[(kk * CIN + cin) * G4 + cout];
    else           v = Wh[(kk * FF + (cin - CIN)) * G4 + cout];
    Wf[i] = v;
}

__global__ void zero_kernel(float* __restrict__ p, int n) {
    int i = blockIdx.x * blockDim.x + threadIdx.x;
    if (i < n) p[i] = 0.0f;
}

// ---------------- fused conv GEMM: z = conv3x3([x_t ; h], Wf) ----------------
// M = B*H*W positions (8x8 spatial tiles), N = 256 gate channels, K = 864.
// Block: 64 positions x 64 channels, Ktile = 16. 256 threads, 4x4 per thread.
__global__ __launch_bounds__(256) void conv_gemm_kernel(
    const float* __restrict__ x,    // [B,T,H,W,CIN]
    const float* __restrict__ h,    // [B,H,W,FF]
    const float* __restrict__ Wf,   // [3,3,CK,G4]
    float* __restrict__ z,          // [B,H,W,G4]
    int t)
{
    __shared__ float As[16][68];
    __shared__ float Bs[16][68];

    const int bidx = blockIdx.x;          // 0..511 spatial tile id
    const int n0   = blockIdx.y << 6;     // channel tile base (0,64,128,192)
    const int b    = bidx >> 6;
    const int y0   = ((bidx >> 3) & 7) << 3;
    const int x0   = (bidx & 7) << 3;

    const int tid = threadIdx.x;
    const int tr  = tid >> 4;   // 0..15 -> position sub-tile
    const int tc  = tid & 15;   // 0..15 -> channel sub-tile

    // A-tile load mapping: thread loads float4 of input channels for one position
    const int pa  = tid >> 2;          // 0..63 position within tile
    const int pay = pa >> 3;
    const int pax = pa & 7;
    const int cia = (tid & 3) << 2;    // 0,4,8,12 channel-in-chunk

    // B-tile load mapping
    const int kb  = tid >> 4;          // 0..15 k within chunk
    const int cob = (tid & 15) << 2;   // cout offset in tile

    const float* xbase = x + (size_t)(b * TT + t) * HW * CIN;
    const float* hbase = h + (size_t)b * HW * FF;

    float acc[4][4] = {};

    for (int kk = 0; kk < 9; ++kk) {
        const int ky = kk / 3 - 1;
        const int kx = kk % 3 - 1;
        const int ya = y0 + pay + ky;
        const int xa = x0 + pax + kx;
        const bool inb = ((unsigned)ya < (unsigned)HH) && ((unsigned)xa < (unsigned)WW);
        const int sp = ya * WW + xa;

        #pragma unroll
        for (int cc = 0; cc < 6; ++cc) {
            const int c0 = cc << 4;
            // ---- load A chunk (im2col gather) ----
            float4 v = make_float4(0.f, 0.f, 0.f, 0.f);
            if (inb) {
                const int c = c0 + cia;
                if (c < CIN) v = *(const float4*)(xbase + (size_t)sp * CIN + c);
                else         v = *(const float4*)(hbase + (size_t)sp * FF + (c - CIN));
            }
            As[cia + 0][pa] = v.x;
            As[cia + 1][pa] = v.y;
            As[cia + 2][pa] = v.z;
            As[cia + 3][pa] = v.w;
            // ---- load B chunk (weights) ----
            const float4 w = *(const float4*)(Wf + (size_t)((kk * CK + c0 + kb) * G4) + n0 + cob);
            *(float4*)&Bs[kb][cob] = w;
            __syncthreads();

            // ---- 16-deep K inner product ----
            #pragma unroll
            for (int k = 0; k < 16; ++k) {
                const float4 a  = *(const float4*)&As[k][tr << 2];
                const float4 bv = *(const float4*)&Bs[k][tc << 2];
                acc[0][0] += a.x * bv.x; acc[0][1] += a.x * bv.y;
                acc[0][2] += a.x * bv.z; acc[0][3] += a.x * bv.w;
                acc[1][0] += a.y * bv.x; acc[1][1] += a.y * bv.y;
                acc[1][2] += a.y * bv.z; acc[1][3] += a.y * bv.w;
                acc[2][0] += a.z * bv.x; acc[2][1] += a.z * bv.y;
                acc[2][2] += a.z * bv.z; acc[2][3] += a.z * bv.w;
                acc[3][0] += a.w * bv.x; acc[3][1] += a.w * bv.y;
                acc[3][2] += a.w * bv.z; acc[3][3] += a.w * bv.w;
            }
            __syncthreads();
        }
    }

    // ---- write z ----
    #pragma unroll
    for (int i = 0; i < 4; ++i) {
        const int p  = (tr << 2) + i;
        const int py = p >> 3;
        const int px = p & 7;
        float4 o = make_float4(acc[i][0], acc[i][1], acc[i][2], acc[i][3]);
        *(float4*)(z + ((size_t)(b * HW) + (y0 + py) * WW + (x0 + px)) * G4 + n0 + (tc << 2)) = o;
    }
}

// ---------------- pointwise LSTM gate + state update -------------------------
__global__ __launch_bounds__(256) void lstm_point_kernel(
    const float* __restrict__ z,     // [B,H,W,256]
    const float* __restrict__ bvec,  // [256]
    float* __restrict__ h,           // [B,H,W,64]
    float* __restrict__ c,           // [B,H,W,64]
    float* __restrict__ out,         // [B,T,H,W,128]
    int t, int chOff)
{
    const int i = blockIdx.x * blockDim.x + threadIdx.x;
    if (i >= STATE_N) return;
    const int f = i & 63;
    const int p = i >> 6;     // b*4096 + y*64 + x

    const float* zp = z + (size_t)p * G4;
    const float zi = zp[f]       + bvec[f];
    const float zf = zp[64 + f]  + bvec[64 + f];
    const float zc = zp[128 + f] + bvec[128 + f];
    const float zo = zp[192 + f] + bvec[192 + f];

    const float ig = fminf(fmaxf(0.2f * zi + 0.5f, 0.f), 1.f);
    const float fg = fminf(fmaxf(0.2f * zf + 0.5f, 0.f), 1.f);
    const float og = fminf(fmaxf(0.2f * zo + 0.5f, 0.f), 1.f);

    const float cn = fg * c[i] + ig * tanhf(zc);
    c[i] = cn;
    const float hn = og * tanhf(cn);
    h[i] = hn;

    const int b  = p >> 12;
    const int yx = p & 4095;
    out[((size_t)(b * TT + t) * HW + yx) * 128 + chOff + f] = hn;
}

// ---------------- driver ------------------------------------------------------
extern "C" void kernel_launch(void* const* d_in, const int* in_sizes, int n_in,
                              void* d_out, int out_size) {
    const float* x    = (const float*)d_in[0];
    const float* Wx_f = (const float*)d_in[1];
    const float* Wh_f = (const float*)d_in[2];
    const float* b_f  = (const float*)d_in[3];
    const float* Wx_b = (const float*)d_in[4];
    const float* Wh_b = (const float*)d_in[5];
    const float* b_b  = (const float*)d_in[6];
    float* out = (float*)d_out;

    float *wf, *hst, *cst, *zst;
    cudaGetSymbolAddress((void**)&wf,  g_Wf);
    cudaGetSymbolAddress((void**)&hst, g_h);
    cudaGetSymbolAddress((void**)&cst, g_c);
    cudaGetSymbolAddress((void**)&zst, g_z);

    float* wf_f = wf;
    float* wf_b = wf + WF_N;
    float* h_f  = hst;
    float* h_b  = hst + STATE_N;
    float* c_f  = cst;
    float* c_b  = cst + STATE_N;
    float* z_f  = zst;
    float* z_b  = zst + Z_N;

    // fuse weights (both directions)
    {
        int nb = (WF_N + 255) / 256;
        fuse_weights_kernel<<<nb, 256>>>(Wx_f, Wh_f, wf_f);
        fuse_weights_kernel<<<nb, 256>>>(Wx_b, Wh_b, wf_b);
    }
    // zero states
    {
        int nb = (STATE_N + 255) / 256;
        zero_kernel<<<nb, 256>>>(h_f, STATE_N);
        zero_kernel<<<nb, 256>>>(c_f, STATE_N);
        zero_kernel<<<nb, 256>>>(h_b, STATE_N);
        zero_kernel<<<nb, 256>>>(c_b, STATE_N);
    }

    const dim3 gemm_grid(512, 4);
    const int point_blocks = (STATE_N + 255) / 256;

    for (int s = 0; s < TT; ++s) {
        // forward direction: time index s, output channels [0,64)
        conv_gemm_kernel<<<gemm_grid, 256>>>(x, h_f, wf_f, z_f, s);
        lstm_point_kernel<<<point_blocks, 256>>>(z_f, b_f, h_f, c_f, out, s, 0);
        // backward direction: consumes x[:, T-1-s], writes out[:, T-1-s, ..., 64:128]
        const int tb = TT - 1 - s;
        conv_gemm_kernel<<<gemm_grid, 256>>>(x, h_b, wf_b, z_b, tb);
        lstm_point_kernel<<<point_blocks, 256>>>(z_b, b_b, h_b, c_b, out, tb, 64);
    }
}

// round 2
// speedup vs baseline: 1.0877x; 1.0877x over previous
#include <cuda_runtime.h>
#include <cuda_bf16.h>
#include <math.h>

// Problem constants
#define BB 8
#define TT 16
#define HH 64
#define WW 64
#define CIN 32
#define FF 64
#define G4 256           // 4*F gate channels
#define CK 96            // CIN + FF fused input channels
#define HW 4096          // H*W
#define STATE_N (BB*HW*FF)
#define Z_N (BB*HW*G4)
#define WF_N (3*3*CK*G4)

#define S_A 132          // As row stride (floats), 528B = 33*16 -> 16B aligned rows
#define S_B 68           // Bs row stride (floats), 272B = 17*16

// ---------------- static device scratch ----------------
__device__ float g_Wf[2][WF_N];
__device__ float g_h[2][STATE_N];
__device__ float g_c[2][STATE_N];
__device__ float g_z[2][Z_N];

// packed f32x2 helpers
#define PACKF2(d, lo, hi) \
    asm("mov.b64 %0, {%1, %2};" : "=l"(d) : "r"(__float_as_uint(lo)), "r"(__float_as_uint(hi)))
#define FFMA2(acc, a, b) \
    asm("fma.rn.f32x2 %0, %1, %2, %0;" : "+l"(acc) : "l"(a), "l"(b))

// ---------------- weight fusion ----------------
__global__ void fuse_weights_kernel(const float* __restrict__ Wx,
                                    const float* __restrict__ Wh,
                                    float* __restrict__ Wf) {
    int i = blockIdx.x * blockDim.x + threadIdx.x;
    if (i >= WF_N) return;
    int cout = i & 255;
    int cin  = (i >> 8) % CK;
    int kk   = i / (256 * CK);
    float v;
    if (cin < CIN) v = Wx[(kk * CIN + cin) * G4 + cout];
    else           v = Wh[(kk * FF + (cin - CIN)) * G4 + cout];
    Wf[i] = v;
}

__global__ void zero_kernel(float* __restrict__ p, int n) {
    int i = blockIdx.x * blockDim.x + threadIdx.x;
    if (i < n) p[i] = 0.0f;
}

// ---------------- fused conv GEMM v2: FFMA2 + double buffering ----------------
// Block tile: 128 positions (8y x 16x) x 64 out channels. 256 threads, 8x4 each.
// K = 9 taps * 96 fused channels = 864, chunked 54 x 16.
__global__ __launch_bounds__(256) void conv_gemm_kernel(
    const float* __restrict__ x,    // [B,T,H,W,CIN]
    const float* __restrict__ h,    // [B,H,W,FF]
    const float* __restrict__ Wf,   // [3,3,CK,G4]
    float* __restrict__ z,          // [B,H,W,G4]
    int t)
{
    __shared__ float As[2][16 * S_A];
    __shared__ float Bs[2][16 * S_B];

    const int bidx = blockIdx.x;          // 0..255 spatial tile
    const int n0   = blockIdx.y << 6;     // out-channel tile base
    const int b    = bidx >> 5;
    const int y0   = ((bidx >> 2) & 7) << 3;   // 8 rows
    const int x0   = (bidx & 3) << 4;          // 16 cols

    const int tid = threadIdx.x;

    // A load mapping: thread owns one position + 8 of the 16 chunk-k channels
    const int pa    = tid & 127;
    const int khalf = (tid >> 7) << 3;    // 0 or 8
    const int pay   = pa >> 4;
    const int pax   = pa & 15;

    // B load mapping
    const int kb  = tid >> 4;             // 0..15
    const int cob = (tid & 15) << 2;

    // compute mapping: 8 positions x 4 channels per thread
    const int tr8 = (tid >> 4) << 3;
    const int tc4 = (tid & 15) << 2;

    const float* xbase = x + (size_t)(b * TT + t) * HW * CIN;
    const float* hbase = h + (size_t)b * HW * FF;
    const float* wbase = Wf + n0;

    unsigned long long acc[4][4];
    #pragma unroll
    for (int i = 0; i < 4; ++i)
        #pragma unroll
        for (int j = 0; j < 4; ++j) acc[i][j] = 0ull;

    float4 ra0, ra1, rb0;

    // fetch chunk (kk, cc) into registers
    auto fetch = [&](int kk, int cc) {
        const int ky = kk / 3 - 1;
        const int kx = kk % 3 - 1;
        const int ya = y0 + pay + ky;
        const int xa = x0 + pax + kx;
        const bool inb = ((unsigned)ya < (unsigned)HH) && ((unsigned)xa < (unsigned)WW);
        ra0 = make_float4(0.f, 0.f, 0.f, 0.f);
        ra1 = ra0;
        if (inb) {
            const int sp = ya * WW + xa;
            const int c  = (cc << 4) + khalf;   // 8-channel group entirely in x or h
            const float* p = (c < CIN) ? (xbase + (size_t)sp * CIN + c)
                                       : (hbase + (size_t)sp * FF + (c - CIN));
            ra0 = *(const float4*)p;
            ra1 = *(const float4*)(p + 4);
        }
        const int kg = kk * CK + (cc << 4) + kb;
        rb0 = *(const float4*)(wbase + (size_t)kg * G4 + cob);
    };

    auto store = [&](int buf) {
        float* ar = &As[buf][0];
        ar[(khalf + 0) * S_A + pa] = ra0.x;
        ar[(khalf + 1) * S_A + pa] = ra0.y;
        ar[(khalf + 2) * S_A + pa] = ra0.z;
        ar[(khalf + 3) * S_A + pa] = ra0.w;
        ar[(khalf + 4) * S_A + pa] = ra1.x;
        ar[(khalf + 5) * S_A + pa] = ra1.y;
        ar[(khalf + 6) * S_A + pa] = ra1.z;
        ar[(khalf + 7) * S_A + pa] = ra1.w;
        *(float4*)&Bs[buf][kb * S_B + cob] = rb0;
    };

    fetch(0, 0);
    store(0);
    __syncthreads();

    int kk = 0, cc = 0;
    #pragma unroll 1
    for (int ch = 0; ch < 54; ++ch) {
        const int cur = ch & 1;
        int kkn = kk, ccn = cc + 1;
        if (ccn == 6) { ccn = 0; kkn++; }
        const bool more = (ch < 53);
        if (more) fetch(kkn, ccn);

        // compute 16-deep K on buffer cur
        #pragma unroll
        for (int k = 0; k < 16; ++k) {
            const float* arow = &As[cur][k * S_A + tr8];
            double2 ap0 = *(const double2*)(arow);
            double2 ap1 = *(const double2*)(arow + 4);
            unsigned long long a01 = __double_as_longlong(ap0.x);
            unsigned long long a23 = __double_as_longlong(ap0.y);
            unsigned long long a45 = __double_as_longlong(ap1.x);
            unsigned long long a67 = __double_as_longlong(ap1.y);
            float4 bv = *(const float4*)&Bs[cur][k * S_B + tc4];
            unsigned long long bd0, bd1, bd2, bd3;
            PACKF2(bd0, bv.x, bv.x);
            PACKF2(bd1, bv.y, bv.y);
            PACKF2(bd2, bv.z, bv.z);
            PACKF2(bd3, bv.w, bv.w);
            FFMA2(acc[0][0], a01, bd0); FFMA2(acc[0][1], a01, bd1);
            FFMA2(acc[0][2], a01, bd2); FFMA2(acc[0][3], a01, bd3);
            FFMA2(acc[1][0], a23, bd0); FFMA2(acc[1][1], a23, bd1);
            FFMA2(acc[1][2], a23, bd2); FFMA2(acc[1][3], a23, bd3);
            FFMA2(acc[2][0], a45, bd0); FFMA2(acc[2][1], a45, bd1);
            FFMA2(acc[2][2], a45, bd2); FFMA2(acc[2][3], a45, bd3);
            FFMA2(acc[3][0], a67, bd0); FFMA2(acc[3][1], a67, bd1);
            FFMA2(acc[3][2], a67, bd2); FFMA2(acc[3][3], a67, bd3);
        }

        if (more) {
            store(cur ^ 1);
            __syncthreads();
        }
        kk = kkn; cc = ccn;
    }

    // epilogue: unpack pairs, write z
    float* zb = z + (size_t)b * HW * G4;
    #pragma unroll
    for (int pp = 0; pp < 4; ++pp) {
        float lo0, hi0, lo1, hi1, lo2, hi2, lo3, hi3;
        asm("mov.b64 {%0,%1}, %2;" : "=r"(*(unsigned*)&lo0), "=r"(*(unsigned*)&hi0) : "l"(acc[pp][0]));
        asm("mov.b64 {%0,%1}, %2;" : "=r"(*(unsigned*)&lo1), "=r"(*(unsigned*)&hi1) : "l"(acc[pp][1]));
        asm("mov.b64 {%0,%1}, %2;" : "=r"(*(unsigned*)&lo2), "=r"(*(unsigned*)&hi2) : "l"(acc[pp][2]));
        asm("mov.b64 {%0,%1}, %2;" : "=r"(*(unsigned*)&lo3), "=r"(*(unsigned*)&hi3) : "l"(acc[pp][3]));
        {
            const int p  = tr8 + 2 * pp;
            const int py = p >> 4, px = p & 15;
            *(float4*)(zb + ((size_t)(y0 + py) * WW + (x0 + px)) * G4 + n0 + tc4)
                = make_float4(lo0, lo1, lo2, lo3);
        }
        {
            const int p  = tr8 + 2 * pp + 1;
            const int py = p >> 4, px = p & 15;
            *(float4*)(zb + ((size_t)(y0 + py) * WW + (x0 + px)) * G4 + n0 + tc4)
                = make_float4(hi0, hi1, hi2, hi3);
        }
    }
}

// ---------------- pointwise LSTM gate + state update ----------------
__global__ __launch_bounds__(256) void lstm_point_kernel(
    const float* __restrict__ z,
    const float* __restrict__ bvec,
    float* __restrict__ h,
    float* __restrict__ c,
    float* __restrict__ out,
    int t, int chOff)
{
    const int i = blockIdx.x * blockDim.x + threadIdx.x;
    if (i >= STATE_N) return;
    const int f = i & 63;
    const int p = i >> 6;

    const float* zp = z + (size_t)p * G4;
    const float zi = zp[f]       + bvec[f];
    const float zf = zp[64 + f]  + bvec[64 + f];
    const float zc = zp[128 + f] + bvec[128 + f];
    const float zo = zp[192 + f] + bvec[192 + f];

    const float ig = fminf(fmaxf(0.2f * zi + 0.5f, 0.f), 1.f);
    const float fg = fminf(fmaxf(0.2f * zf + 0.5f, 0.f), 1.f);
    const float og = fminf(fmaxf(0.2f * zo + 0.5f, 0.f), 1.f);

    const float cn = fg * c[i] + ig * tanhf(zc);
    c[i] = cn;
    const float hn = og * tanhf(cn);
    h[i] = hn;

    const int b  = p >> 12;
    const int yx = p & 4095;
    out[((size_t)(b * TT + t) * HW + yx) * 128 + chOff + f] = hn;
}

// ---------------- driver ----------------
extern "C" void kernel_launch(void* const* d_in, const int* in_sizes, int n_in,
                              void* d_out, int out_size) {
    const float* x    = (const float*)d_in[0];
    const float* Wx_f = (const float*)d_in[1];
    const float* Wh_f = (const float*)d_in[2];
    const float* b_f  = (const float*)d_in[3];
    const float* Wx_b = (const float*)d_in[4];
    const float* Wh_b = (const float*)d_in[5];
    const float* b_b  = (const float*)d_in[6];
    float* out = (float*)d_out;

    float *wf, *hst, *cst, *zst;
    cudaGetSymbolAddress((void**)&wf,  g_Wf);
    cudaGetSymbolAddress((void**)&hst, g_h);
    cudaGetSymbolAddress((void**)&cst, g_c);
    cudaGetSymbolAddress((void**)&zst, g_z);

    float* wf_f = wf;
    float* wf_b = wf + WF_N;
    float* h_f  = hst;
    float* h_b  = hst + STATE_N;
    float* c_f  = cst;
    float* c_b  = cst + STATE_N;
    float* z_f  = zst;
    float* z_b  = zst + Z_N;

    {
        int nb = (WF_N + 255) / 256;
        fuse_weights_kernel<<<nb, 256>>>(Wx_f, Wh_f, wf_f);
        fuse_weights_kernel<<<nb, 256>>>(Wx_b, Wh_b, wf_b);
    }
    {
        int nb = (STATE_N + 255) / 256;
        zero_kernel<<<nb, 256>>>(h_f, STATE_N);
        zero_kernel<<<nb, 256>>>(c_f, STATE_N);
        zero_kernel<<<nb, 256>>>(h_b, STATE_N);
        zero_kernel<<<nb, 256>>>(c_b, STATE_N);
    }

    const dim3 gemm_grid(256, 4);
    const int point_blocks = (STATE_N + 255) / 256;

    for (int s = 0; s < TT; ++s) {
        conv_gemm_kernel<<<gemm_grid, 256>>>(x, h_f, wf_f, z_f, s);
        lstm_point_kernel<<<point_blocks, 256>>>(z_f, b_f, h_f, c_f, out, s, 0);
        const int tb = TT - 1 - s;
        conv_gemm_kernel<<<gemm_grid, 256>>>(x, h_b, wf_b, z_b, tb);
        lstm_point_kernel<<<point_blocks, 256>>>(z_b, b_b, h_b, c_b, out, tb, 64);
    }
}